// round 12
// baseline (speedup 1.0000x reference)
#include <cuda_runtime.h>
#include <cuda_bf16.h>
#include <cuda_fp16.h>
#include <cstdint>

#define NN 100000
#define EE 1600000
#define NSEG (NN * 8)
#define AST 136                 // A smem row stride (bf16): [Ah 64 | Al 64 | pad 8]
#define BST 136                 // B smem row stride (bf16): [Bh 64 | Bl 64 | pad 8]
#define KW 128                  // packed W row: [0,64)=hi, [64,128)=lo
#define SMEM_BYTES (64*AST*2 + 2*64*BST*2)    // 52224

__device__ __align__(16) __half   g_y[(size_t)NN * 512];   // fp16 Y: 102MB, ~L2-resident
__device__ __align__(16) float    g_h[(size_t)NN * 64];
__device__ __align__(16) unsigned g_cnt[NSEG];
__device__ __align__(16) unsigned g_off[NSEG + 1];
__device__ __align__(16) unsigned g_woff[NSEG];
__device__ __align__(16) unsigned g_bsum[512];
__device__ __align__(16) int      g_ssrc[EE];     // sorted by (dst,rel): src*8+rel
__device__ __align__(16) float    g_acc[128];
__device__ __align__(16) float    g_scale[64];
__device__ __align__(16) float    g_shift[64];
__device__ __align__(16) __nv_bfloat16 g_wp1[576 * KW];
__device__ __align__(16) __nv_bfloat16 g_wp2[576 * KW];

// ---------------- prep ----------------
__global__ void hist_kernel(const int* __restrict__ ei, const int* __restrict__ et,
                            unsigned* __restrict__ cnt) {
    int e = blockIdx.x * 256 + threadIdx.x;
    if (e >= EE) return;
    atomicAdd(cnt + ei[EE + e] * 8 + et[e], 1u);
}

__global__ void scan1(const unsigned* __restrict__ cnt, unsigned* __restrict__ off,
                      unsigned* __restrict__ bsum) {
    __shared__ unsigned sh[256];
    int t = threadIdx.x;
    int base = blockIdx.x * 2048 + t * 8;
    unsigned v[8], s = 0;
#pragma unroll
    for (int j = 0; j < 8; j++) { v[j] = (base + j < NSEG) ? cnt[base + j] : 0u; s += v[j]; }
    sh[t] = s; __syncthreads();
    for (int d = 1; d < 256; d <<= 1) {
        unsigned x = (t >= d) ? sh[t - d] : 0u;
        __syncthreads(); sh[t] += x; __syncthreads();
    }
    if (t == 255) bsum[blockIdx.x] = sh[255];
    unsigned run = sh[t] - s;
#pragma unroll
    for (int j = 0; j < 8; j++)
        if (base + j < NSEG) { off[base + j] = run; run += v[j]; }
}

__global__ void scan2(unsigned* bsum, int nb) {
    __shared__ unsigned sh[512];
    int t = threadIdx.x;
    unsigned v = (t < nb) ? bsum[t] : 0u;
    sh[t] = v; __syncthreads();
    for (int d = 1; d < 512; d <<= 1) {
        unsigned x = (t >= d) ? sh[t - d] : 0u;
        __syncthreads(); sh[t] += x; __syncthreads();
    }
    if (t < nb) bsum[t] = sh[t] - v;
}

__global__ void scan3(unsigned* __restrict__ off, unsigned* __restrict__ woff,
                      const unsigned* __restrict__ bsum) {
    int i = blockIdx.x * 256 + threadIdx.x;
    if (i < NSEG) { unsigned o = off[i] + bsum[i >> 11]; off[i] = o; woff[i] = o; }
    if (i == 0) off[NSEG] = EE;
}

__global__ void sort_kernel(const int* __restrict__ ei, const int* __restrict__ et,
                            unsigned* __restrict__ woff, int* __restrict__ ssrc) {
    int e = blockIdx.x * 256 + threadIdx.x;
    if (e >= EE) return;
    int r = et[e];
    int b = ei[EE + e] * 8 + r;
    unsigned pos = atomicAdd(woff + b, 1u);
    ssrc[pos] = ei[e] * 8 + r;
}

// pack W[r,d,o] (+root r==8) -> wp[j=r*64+o][k]: k<64 hi(d=k), else lo(d=k-64)
__global__ void prep_w(const float* __restrict__ w, const float* __restrict__ root,
                       __nv_bfloat16* __restrict__ wp) {
    int i = blockIdx.x * 256 + threadIdx.x;
    if (i >= 576 * KW) return;
    int j = i / KW, k = i % KW;
    int r = j >> 6, o = j & 63;
    int d = k & 63;
    float v = (r < 8) ? w[((size_t)r * 64 + d) * 64 + o] : root[(size_t)d * 64 + o];
    __nv_bfloat16 hi = __float2bfloat16(v);
    wp[i] = (k < 64) ? hi : __float2bfloat16(v - __bfloat162float(hi));
}

// ---------------- GEMM: 64-row blocks, m32n16 warps, ldmatrix frags ----------------
__device__ __forceinline__ uint32_t smem_u32(const void* p) {
    uint32_t a;
    asm("{ .reg .u64 t; cvta.to.shared.u64 t, %1; cvt.u32.u64 %0, t; }" : "=r"(a) : "l"(p));
    return a;
}
__device__ __forceinline__ void cp16(void* dst, const void* src) {
    unsigned s = (unsigned)__cvta_generic_to_shared(dst);
    asm volatile("cp.async.cg.shared.global [%0], [%1], 16;" :: "r"(s), "l"(src));
}
__device__ __forceinline__ void ldsm4(unsigned& r0, unsigned& r1, unsigned& r2, unsigned& r3,
                                      uint32_t addr) {
    asm volatile("ldmatrix.sync.aligned.m8n8.x4.shared.b16 {%0,%1,%2,%3}, [%4];"
                 : "=r"(r0), "=r"(r1), "=r"(r2), "=r"(r3) : "r"(addr));
}

__device__ __forceinline__ void issue_b_chunk(__nv_bfloat16* bbuf,
                                              const __nv_bfloat16* wp, int nc, int tid) {
    const __nv_bfloat16* src0 = wp + (size_t)nc * 64 * KW;
#pragma unroll
    for (int i = 0; i < 4; i++) {
        int t = tid + i * 256;          // 1024 = 64 rows x 16 segs of 8 bf16
        int j = t >> 4, sg = t & 15;
        cp16(bbuf + j * BST + sg * 8, src0 + j * KW + sg * 8);
    }
}

#define MMA16816(c0,c1,c2,c3,a0,a1,a2,a3,b0,b1)                                     \
    asm volatile("mma.sync.aligned.m16n8k16.row.col.f32.bf16.bf16.f32 "             \
                 "{%0,%1,%2,%3},{%4,%5,%6,%7},{%8,%9},{%0,%1,%2,%3};"               \
                 : "+f"(c0), "+f"(c1), "+f"(c2), "+f"(c3)                           \
                 : "r"(a0), "r"(a1), "r"(a2), "r"(a3), "r"(b0), "r"(b1))

template <bool APPLY_BN>
__global__ void __launch_bounds__(256)
gemm_kernel(const float* __restrict__ X, const __nv_bfloat16* __restrict__ WP,
            const float* __restrict__ bias,
            const float* __restrict__ bnscale, const float* __restrict__ bnshift,
            __half* __restrict__ Y, float* __restrict__ OUT) {
    extern __shared__ char smem[];
    __nv_bfloat16* As = (__nv_bfloat16*)smem;                      // [64][AST]
    __nv_bfloat16* Bs = (__nv_bfloat16*)(smem + 64 * AST * 2);     // 2 x [64][BST]

    const int tid = threadIdx.x;
    const int wid = tid >> 5, lane = tid & 31;
    const int g = lane >> 2, tig = lane & 3;
    const int warpM = wid & 1, warpN = wid >> 1;      // m32 x n16 warp tiles
    const int mbase = blockIdx.x * 64;
    const int mat = lane >> 3, rl = lane & 7;

    issue_b_chunk(Bs, WP, 0, tid);
    asm volatile("cp.async.commit_group;");

    // A fill: 64 rows x 32 float2
    for (int it = tid; it < 64 * 32; it += 256) {
        int row = it >> 5, dp = it & 31;
        int grow = mbase + row;
        float2 v = make_float2(0.f, 0.f);
        if (grow < NN) v = *(const float2*)(X + (size_t)grow * 64 + dp * 2);
        if (APPLY_BN) {
            v.x = fmaxf(v.x * bnscale[dp * 2]     + bnshift[dp * 2], 0.f);
            v.y = fmaxf(v.y * bnscale[dp * 2 + 1] + bnshift[dp * 2 + 1], 0.f);
        }
        __nv_bfloat162 hi, lo;
        hi.x = __float2bfloat16(v.x); hi.y = __float2bfloat16(v.y);
        lo.x = __float2bfloat16(v.x - __bfloat162float(hi.x));
        lo.y = __float2bfloat16(v.y - __bfloat162float(hi.y));
        __nv_bfloat162* arow = (__nv_bfloat162*)(As + row * AST);
        arow[dp] = hi; arow[32 + dp] = lo;
    }
    __syncthreads();

    // A frags -> registers ONCE via ldmatrix (m32 = 2 mt tiles, 4 kt, hi/lo)
    const uint32_t as_u = smem_u32(As);
    unsigned ah[2][4][4], al[2][4][4];
#pragma unroll
    for (int mt = 0; mt < 2; mt++) {
#pragma unroll
        for (int kt = 0; kt < 4; kt++) {
            uint32_t row = warpM * 32 + mt * 16 + (mat & 1) * 8 + rl;
            uint32_t kc  = kt * 16 + (mat >> 1) * 8;
            uint32_t ad = as_u + (row * AST + kc) * 2;
            ldsm4(ah[mt][kt][0], ah[mt][kt][1], ah[mt][kt][2], ah[mt][kt][3], ad);
            ldsm4(al[mt][kt][0], al[mt][kt][1], al[mt][kt][2], al[mt][kt][3], ad + 128);
        }
    }

    float c[2][2][4];
#pragma unroll
    for (int mt = 0; mt < 2; mt++)
#pragma unroll
        for (int nt = 0; nt < 2; nt++)
#pragma unroll
            for (int k = 0; k < 4; k++) c[mt][nt][k] = 0.f;

    const uint32_t bs_u = smem_u32(Bs);

    for (int nc = 0; nc < 9; nc++) {
        if (nc + 1 < 9) {
            issue_b_chunk(Bs + ((nc + 1) & 1) * 64 * BST, WP, nc + 1, tid);
            asm volatile("cp.async.commit_group;");
            asm volatile("cp.async.wait_group 1;");
        } else {
            asm volatile("cp.async.wait_group 0;");
        }
        __syncthreads();

        // B frag rows for ldmatrix: n16 slice, mats: (n half, k half)
        uint32_t brow = warpN * 16 + (mat >> 1) * 8 + rl;
        uint32_t bbase = bs_u + ((nc & 1) * 64 * BST + brow * BST) * 2;
#pragma unroll
        for (int kt = 0; kt < 4; kt++) {
            uint32_t kc = kt * 16 + (mat & 1) * 8;
            unsigned bh[4], bl[4];
            ldsm4(bh[0], bh[1], bh[2], bh[3], bbase + kc * 2);          // nt0: bh0,bh1; nt1: bh2,bh3
            ldsm4(bl[0], bl[1], bl[2], bl[3], bbase + (64 + kc) * 2);
#pragma unroll
            for (int mt = 0; mt < 2; mt++)
#pragma unroll
                for (int nt = 0; nt < 2; nt++) {
                    MMA16816(c[mt][nt][0], c[mt][nt][1], c[mt][nt][2], c[mt][nt][3],
                             ah[mt][kt][0], ah[mt][kt][1], ah[mt][kt][2], ah[mt][kt][3],
                             bh[nt * 2], bh[nt * 2 + 1]);
                    MMA16816(c[mt][nt][0], c[mt][nt][1], c[mt][nt][2], c[mt][nt][3],
                             al[mt][kt][0], al[mt][kt][1], al[mt][kt][2], al[mt][kt][3],
                             bh[nt * 2], bh[nt * 2 + 1]);
                    MMA16816(c[mt][nt][0], c[mt][nt][1], c[mt][nt][2], c[mt][nt][3],
                             ah[mt][kt][0], ah[mt][kt][1], ah[mt][kt][2], ah[mt][kt][3],
                             bl[nt * 2], bl[nt * 2 + 1]);
                }
        }
        __syncthreads();

        // epilogue for this 64-col chunk
#pragma unroll
        for (int mt = 0; mt < 2; mt++) {
            int row = mbase + warpM * 32 + mt * 16 + g;
#pragma unroll
            for (int nt = 0; nt < 2; nt++) {
                int col = warpN * 16 + nt * 8 + 2 * tig;
                float* cc = c[mt][nt];
                if (nc < 8) {
                    size_t base = (size_t)row * 512 + nc * 64 + col;
                    if (row < NN)
                        *(__half2*)(Y + base) = __floats2half2_rn(cc[0], cc[1]);
                    if (row + 8 < NN)
                        *(__half2*)(Y + base + 8 * 512) = __floats2half2_rn(cc[2], cc[3]);
                } else {
                    float2 bb = *(const float2*)(bias + col);
                    if (row < NN)
                        *(float2*)(OUT + (size_t)row * 64 + col) = make_float2(cc[0] + bb.x, cc[1] + bb.y);
                    if (row + 8 < NN)
                        *(float2*)(OUT + (size_t)(row + 8) * 64 + col) = make_float2(cc[2] + bb.x, cc[3] + bb.y);
                }
                cc[0] = cc[1] = cc[2] = cc[3] = 0.f;
            }
        }
    }
}

// ---------------- scatter: warp-per-dst segment reduce, fp16 Y ----------------
__global__ void __launch_bounds__(256)
scatter_kernel(const __half* __restrict__ Y, const unsigned* __restrict__ off,
               const int* __restrict__ ssrc, float* __restrict__ OUT) {
    int node = blockIdx.x * 8 + (threadIdx.x >> 5);
    if (node >= NN) return;
    int lane = threadIdx.x & 31;

    unsigned ov = (lane < 9) ? __ldg(off + (size_t)node * 8 + lane) : 0u;
    unsigned onext = __shfl_down_sync(0xffffffffu, ov, 1);
    float invv = 1.0f / fmaxf((float)(onext - ov), 1.0f);
    unsigned o0 = __shfl_sync(0xffffffffu, ov, 0);
    unsigned o8 = __shfl_sync(0xffffffffu, ov, 8);

    float accx = 0.f, accy = 0.f;
    for (unsigned e = o0; e < o8; e += 4) {
        int sa[4];
#pragma unroll
        for (int j = 0; j < 4; j++)
            sa[j] = (e + j < o8) ? __ldg(ssrc + e + j) : -1;
        float2 v[4];
#pragma unroll
        for (int j = 0; j < 4; j++) {
            v[j] = make_float2(0.f, 0.f);
            if (sa[j] >= 0) {
                __half2 hv = *(const __half2*)(Y + (size_t)sa[j] * 64 + lane * 2);
                v[j] = __half22float2(hv);
            }
        }
#pragma unroll
        for (int j = 0; j < 4; j++) {
            if (sa[j] >= 0) {
                float iv = __shfl_sync(0xffffffffu, invv, sa[j] & 7);
                accx += v[j].x * iv; accy += v[j].y * iv;
            }
        }
    }
    float2* op = (float2*)(OUT + (size_t)node * 64 + lane * 2);
    float2 cur = *op;
    *op = make_float2(cur.x + accx, cur.y + accy);
}

// ---------------- batch norm ----------------
__global__ void bn_stats(const float* __restrict__ H, float* __restrict__ acc) {
    int ch = threadIdx.x & 63, ry = threadIdx.x >> 6;
    float s = 0.f, q = 0.f;
    for (int r = blockIdx.x * 4 + ry; r < NN; r += gridDim.x * 4) {
        float v = H[(size_t)r * 64 + ch];
        s += v; q += v * v;
    }
    __shared__ float sh[2][4][64];
    sh[0][ry][ch] = s; sh[1][ry][ch] = q;
    __syncthreads();
    if (ry == 0) {
        s = sh[0][0][ch] + sh[0][1][ch] + sh[0][2][ch] + sh[0][3][ch];
        q = sh[1][0][ch] + sh[1][1][ch] + sh[1][2][ch] + sh[1][3][ch];
        atomicAdd(acc + ch, s);
        atomicAdd(acc + 64 + ch, q);
    }
}

__global__ void bn_final(const float* __restrict__ acc, const float* __restrict__ gamma,
                         const float* __restrict__ beta,
                         float* __restrict__ scale, float* __restrict__ shift) {
    int ch = threadIdx.x;
    if (ch >= 64) return;
    const float invN = 1.0f / (float)NN;
    float mu = acc[ch] * invN;
    float var = acc[64 + ch] * invN - mu * mu;
    float sc = gamma[ch] * rsqrtf(var + 1e-5f);
    scale[ch] = sc;
    shift[ch] = beta[ch] - mu * sc;
}

// ---------------- launcher ----------------
extern "C" void kernel_launch(void* const* d_in, const int* in_sizes, int n_in,
                              void* d_out, int out_size) {
    const float* x      = (const float*)d_in[0];
    const int*   ei     = (const int*)d_in[1];
    const int*   etype  = (const int*)d_in[2];
    const float* w1     = (const float*)d_in[3];
    const float* root1  = (const float*)d_in[4];
    const float* b1     = (const float*)d_in[5];
    const float* gamma1 = (const float*)d_in[6];
    const float* beta1  = (const float*)d_in[7];
    const float* w2     = (const float*)d_in[8];
    const float* root2  = (const float*)d_in[9];
    const float* b2     = (const float*)d_in[10];
    float* out = (float*)d_out;

    __half *y;
    float *h, *acc, *scale, *shift;
    unsigned *cnt, *off, *woff, *bsum;
    int *ssrc;
    __nv_bfloat16 *wp1, *wp2;
    cudaGetSymbolAddress((void**)&y, g_y);
    cudaGetSymbolAddress((void**)&h, g_h);
    cudaGetSymbolAddress((void**)&cnt, g_cnt);
    cudaGetSymbolAddress((void**)&off, g_off);
    cudaGetSymbolAddress((void**)&woff, g_woff);
    cudaGetSymbolAddress((void**)&bsum, g_bsum);
    cudaGetSymbolAddress((void**)&ssrc, g_ssrc);
    cudaGetSymbolAddress((void**)&acc, g_acc);
    cudaGetSymbolAddress((void**)&scale, g_scale);
    cudaGetSymbolAddress((void**)&shift, g_shift);
    cudaGetSymbolAddress((void**)&wp1, g_wp1);
    cudaGetSymbolAddress((void**)&wp2, g_wp2);

    cudaFuncSetAttribute(gemm_kernel<false>, cudaFuncAttributeMaxDynamicSharedMemorySize, SMEM_BYTES);
    cudaFuncSetAttribute(gemm_kernel<true>,  cudaFuncAttributeMaxDynamicSharedMemorySize, SMEM_BYTES);

    const int MT = (NN + 63) / 64;             // 1563
    const int NB1 = (NSEG + 2047) / 2048;      // 391

    cudaMemsetAsync(cnt, 0, NSEG * sizeof(unsigned), 0);
    cudaMemsetAsync(acc, 0, 128 * sizeof(float), 0);

    prep_w<<<(576 * KW + 255) / 256, 256>>>(w1, root1, wp1);   // 1
    prep_w<<<(576 * KW + 255) / 256, 256>>>(w2, root2, wp2);   // 2
    hist_kernel<<<(EE + 255) / 256, 256>>>(ei, etype, cnt);    // 3
    gemm_kernel<false><<<MT, 256, SMEM_BYTES>>>(x, wp1, b1, nullptr, nullptr, y, h); // 4 (profiled)
    scan1<<<NB1, 256>>>(cnt, off, bsum);                       // 5
    scan2<<<1, 512>>>(bsum, NB1);                              // 6
    scan3<<<(NSEG + 255) / 256, 256>>>(off, woff, bsum);       // 7
    sort_kernel<<<(EE + 255) / 256, 256>>>(ei, etype, woff, ssrc); // 8
    scatter_kernel<<<(NN + 7) / 8, 256>>>(y, off, ssrc, h);    // 9
    bn_stats<<<1024, 256>>>(h, acc);                           // 10
    bn_final<<<1, 64>>>(acc, gamma1, beta1, scale, shift);     // 11
    gemm_kernel<true><<<MT, 256, SMEM_BYTES>>>(h, wp2, b2, scale, shift, y, out); // 12
    scatter_kernel<<<(NN + 7) / 8, 256>>>(y, off, ssrc, out);  // 13
}

// round 13
// speedup vs baseline: 1.0600x; 1.0600x over previous
#include <cuda_runtime.h>
#include <cuda_bf16.h>
#include <cuda_fp16.h>
#include <cstdint>

#define NN 100000
#define EE 1600000
#define NSEG (NN * 8)
#define AST 136                 // A smem row stride (bf16): [Ah 64 | Al 64 | pad 8]
#define SMEM_BYTES (64*AST*2)   // 17408 — A only, no B staging

__device__ __align__(16) __half   g_y[(size_t)NN * 512];
__device__ __align__(16) float    g_h[(size_t)NN * 64];
__device__ __align__(16) unsigned g_cnt[NSEG];
__device__ __align__(16) unsigned g_off[NSEG + 1];
__device__ __align__(16) unsigned g_woff[NSEG];
__device__ __align__(16) unsigned g_bsum[512];
__device__ __align__(16) int      g_ssrc[EE];
__device__ __align__(16) float    g_acc[128];
__device__ __align__(16) float    g_scale[64];
__device__ __align__(16) float    g_shift[64];
// fragment-packed W: [nc 9][ns 4][kt 4][hb 2][lane 32][reg 4][pair 2] bf16 = 147KB
__device__ __align__(16) __nv_bfloat16 g_wp1[9 * 8192];
__device__ __align__(16) __nv_bfloat16 g_wp2[9 * 8192];

// ---------------- prep ----------------
__global__ void hist_kernel(const int* __restrict__ ei, const int* __restrict__ et,
                            unsigned* __restrict__ cnt) {
    int e = blockIdx.x * 256 + threadIdx.x;
    if (e >= EE) return;
    atomicAdd(cnt + ei[EE + e] * 8 + et[e], 1u);
}

__global__ void scan1(const unsigned* __restrict__ cnt, unsigned* __restrict__ off,
                      unsigned* __restrict__ bsum) {
    __shared__ unsigned sh[256];
    int t = threadIdx.x;
    int base = blockIdx.x * 2048 + t * 8;
    unsigned v[8], s = 0;
#pragma unroll
    for (int j = 0; j < 8; j++) { v[j] = (base + j < NSEG) ? cnt[base + j] : 0u; s += v[j]; }
    sh[t] = s; __syncthreads();
    for (int d = 1; d < 256; d <<= 1) {
        unsigned x = (t >= d) ? sh[t - d] : 0u;
        __syncthreads(); sh[t] += x; __syncthreads();
    }
    if (t == 255) bsum[blockIdx.x] = sh[255];
    unsigned run = sh[t] - s;
#pragma unroll
    for (int j = 0; j < 8; j++)
        if (base + j < NSEG) { off[base + j] = run; run += v[j]; }
}

__global__ void scan2(unsigned* bsum, int nb) {
    __shared__ unsigned sh[512];
    int t = threadIdx.x;
    unsigned v = (t < nb) ? bsum[t] : 0u;
    sh[t] = v; __syncthreads();
    for (int d = 1; d < 512; d <<= 1) {
        unsigned x = (t >= d) ? sh[t - d] : 0u;
        __syncthreads(); sh[t] += x; __syncthreads();
    }
    if (t < nb) bsum[t] = sh[t] - v;
}

__global__ void scan3(unsigned* __restrict__ off, unsigned* __restrict__ woff,
                      const unsigned* __restrict__ bsum) {
    int i = blockIdx.x * 256 + threadIdx.x;
    if (i < NSEG) { unsigned o = off[i] + bsum[i >> 11]; off[i] = o; woff[i] = o; }
    if (i == 0) off[NSEG] = EE;
}

__global__ void sort_kernel(const int* __restrict__ ei, const int* __restrict__ et,
                            unsigned* __restrict__ woff, int* __restrict__ ssrc) {
    int e = blockIdx.x * 256 + threadIdx.x;
    if (e >= EE) return;
    int r = et[e];
    int b = ei[EE + e] * 8 + r;
    unsigned pos = atomicAdd(woff + b, 1u);
    ssrc[pos] = ei[e] * 8 + r;
}

// fragment-pack W (+root as rel 8) for direct LDG.128 B-fragment loads.
// layout elem idx: ((((nc*4+ns)*4+kt)*2+hb)*32 + lane)*8 + r*2 + p
__global__ void prep_w(const float* __restrict__ w, const float* __restrict__ root,
                       __nv_bfloat16* __restrict__ wp) {
    int i = blockIdx.x * 256 + threadIdx.x;
    if (i >= 9 * 8192) return;
    int nc = i >> 13;
    int rem = i & 8191;
    int ns = rem >> 11;
    int rem2 = rem & 2047;
    int kt = rem2 >> 9;
    int rem3 = rem2 & 511;
    int hb = rem3 >> 8;
    int rem4 = rem3 & 255;
    int lane = rem4 >> 3;
    int q = rem4 & 7;
    int r = q >> 1, p = q & 1;
    int n_local = ns * 16 + (r >> 1) * 8 + (lane >> 2);
    int j = nc * 64 + n_local;                       // packed row: rel*64 + o
    int k = kt * 16 + (lane & 3) * 2 + (r & 1) * 8 + p;  // input dim d
    int rel = j >> 6, o = j & 63;
    float v = (rel < 8) ? w[((size_t)rel * 64 + k) * 64 + o] : root[(size_t)k * 64 + o];
    __nv_bfloat16 hi = __float2bfloat16(v);
    wp[i] = (hb == 0) ? hi : __float2bfloat16(v - __bfloat162float(hi));
}

// ---------------- GEMM: barrier-free, A in regs, B frags via LDG from L2 ----------------
__device__ __forceinline__ uint32_t smem_u32(const void* p) {
    uint32_t a;
    asm("{ .reg .u64 t; cvta.to.shared.u64 t, %1; cvt.u32.u64 %0, t; }" : "=r"(a) : "l"(p));
    return a;
}
__device__ __forceinline__ void ldsm4(unsigned& r0, unsigned& r1, unsigned& r2, unsigned& r3,
                                      uint32_t addr) {
    asm volatile("ldmatrix.sync.aligned.m8n8.x4.shared.b16 {%0,%1,%2,%3}, [%4];"
                 : "=r"(r0), "=r"(r1), "=r"(r2), "=r"(r3) : "r"(addr));
}

#define MMA16816(c0,c1,c2,c3,a0,a1,a2,a3,b0,b1)                                     \
    asm volatile("mma.sync.aligned.m16n8k16.row.col.f32.bf16.bf16.f32 "             \
                 "{%0,%1,%2,%3},{%4,%5,%6,%7},{%8,%9},{%0,%1,%2,%3};"               \
                 : "+f"(c0), "+f"(c1), "+f"(c2), "+f"(c3)                           \
                 : "r"(a0), "r"(a1), "r"(a2), "r"(a3), "r"(b0), "r"(b1))

template <bool APPLY_BN>
__global__ void __launch_bounds__(256, 2)
gemm_kernel(const float* __restrict__ X, const __nv_bfloat16* __restrict__ WP,
            const float* __restrict__ bias,
            const float* __restrict__ bnscale, const float* __restrict__ bnshift,
            __half* __restrict__ Y, float* __restrict__ OUT) {
    extern __shared__ char smem[];
    __nv_bfloat16* As = (__nv_bfloat16*)smem;          // [64][AST]

    const int tid = threadIdx.x;
    const int wid = tid >> 5, lane = tid & 31;
    const int g = lane >> 2, tig = lane & 3;
    const int warpM = wid & 1, ns = wid >> 1;          // m32 x n16 warp tiles
    const int mbase = blockIdx.x * 64;
    const int mat = lane >> 3, rl = lane & 7;

    // A fill: 64 rows x 32 float2
    for (int it = tid; it < 64 * 32; it += 256) {
        int row = it >> 5, dp = it & 31;
        int grow = mbase + row;
        float2 v = make_float2(0.f, 0.f);
        if (grow < NN) v = *(const float2*)(X + (size_t)grow * 64 + dp * 2);
        if (APPLY_BN) {
            v.x = fmaxf(v.x * bnscale[dp * 2]     + bnshift[dp * 2], 0.f);
            v.y = fmaxf(v.y * bnscale[dp * 2 + 1] + bnshift[dp * 2 + 1], 0.f);
        }
        __nv_bfloat162 hi, lo;
        hi.x = __float2bfloat16(v.x); hi.y = __float2bfloat16(v.y);
        lo.x = __float2bfloat16(v.x - __bfloat162float(hi.x));
        lo.y = __float2bfloat16(v.y - __bfloat162float(hi.y));
        __nv_bfloat162* arow = (__nv_bfloat162*)(As + row * AST);
        arow[dp] = hi; arow[32 + dp] = lo;
    }
    __syncthreads();    // the ONLY block barrier

    // A frags -> registers once via ldmatrix
    const uint32_t as_u = smem_u32(As);
    unsigned ah[2][4][4], al[2][4][4];
#pragma unroll
    for (int mt = 0; mt < 2; mt++) {
#pragma unroll
        for (int kt = 0; kt < 4; kt++) {
            uint32_t row = warpM * 32 + mt * 16 + (mat & 1) * 8 + rl;
            uint32_t kc  = kt * 16 + (mat >> 1) * 8;
            uint32_t ad = as_u + (row * AST + kc) * 2;
            ldsm4(ah[mt][kt][0], ah[mt][kt][1], ah[mt][kt][2], ah[mt][kt][3], ad);
            ldsm4(al[mt][kt][0], al[mt][kt][1], al[mt][kt][2], al[mt][kt][3], ad + 128);
        }
    }

    float c[2][2][4];
#pragma unroll
    for (int mt = 0; mt < 2; mt++)
#pragma unroll
        for (int nt = 0; nt < 2; nt++)
#pragma unroll
            for (int k = 0; k < 4; k++) c[mt][nt][k] = 0.f;

    // per-warp fragment base: ((((nc*4+ns)*4+kt)*2+hb)*32 + lane) uint4s
    const uint4* wf = (const uint4*)WP;

#pragma unroll 1
    for (int nc = 0; nc < 9; nc++) {
        const uint4* pc = wf + (((size_t)nc * 4 + ns) * 4) * 64 + lane;
#pragma unroll
        for (int kt = 0; kt < 4; kt++) {
            uint4 bh = __ldg(pc + (kt * 2 + 0) * 32);
            uint4 bl = __ldg(pc + (kt * 2 + 1) * 32);
#pragma unroll
            for (int mt = 0; mt < 2; mt++) {
                MMA16816(c[mt][0][0], c[mt][0][1], c[mt][0][2], c[mt][0][3],
                         ah[mt][kt][0], ah[mt][kt][1], ah[mt][kt][2], ah[mt][kt][3],
                         bh.x, bh.y);
                MMA16816(c[mt][1][0], c[mt][1][1], c[mt][1][2], c[mt][1][3],
                         ah[mt][kt][0], ah[mt][kt][1], ah[mt][kt][2], ah[mt][kt][3],
                         bh.z, bh.w);
                MMA16816(c[mt][0][0], c[mt][0][1], c[mt][0][2], c[mt][0][3],
                         al[mt][kt][0], al[mt][kt][1], al[mt][kt][2], al[mt][kt][3],
                         bh.x, bh.y);
                MMA16816(c[mt][1][0], c[mt][1][1], c[mt][1][2], c[mt][1][3],
                         al[mt][kt][0], al[mt][kt][1], al[mt][kt][2], al[mt][kt][3],
                         bh.z, bh.w);
                MMA16816(c[mt][0][0], c[mt][0][1], c[mt][0][2], c[mt][0][3],
                         ah[mt][kt][0], ah[mt][kt][1], ah[mt][kt][2], ah[mt][kt][3],
                         bl.x, bl.y);
                MMA16816(c[mt][1][0], c[mt][1][1], c[mt][1][2], c[mt][1][3],
                         ah[mt][kt][0], ah[mt][kt][1], ah[mt][kt][2], ah[mt][kt][3],
                         bl.z, bl.w);
            }
        }

        // epilogue for this 64-col chunk (no barrier needed — private C regs)
#pragma unroll
        for (int mt = 0; mt < 2; mt++) {
            int row = mbase + warpM * 32 + mt * 16 + g;
#pragma unroll
            for (int nt = 0; nt < 2; nt++) {
                int col = ns * 16 + nt * 8 + 2 * tig;
                float* cc = c[mt][nt];
                if (nc < 8) {
                    size_t base = (size_t)row * 512 + nc * 64 + col;
                    if (row < NN)
                        *(__half2*)(Y + base) = __floats2half2_rn(cc[0], cc[1]);
                    if (row + 8 < NN)
                        *(__half2*)(Y + base + 8 * 512) = __floats2half2_rn(cc[2], cc[3]);
                } else {
                    float2 bb = *(const float2*)(bias + col);
                    if (row < NN)
                        *(float2*)(OUT + (size_t)row * 64 + col) = make_float2(cc[0] + bb.x, cc[1] + bb.y);
                    if (row + 8 < NN)
                        *(float2*)(OUT + (size_t)(row + 8) * 64 + col) = make_float2(cc[2] + bb.x, cc[3] + bb.y);
                }
                cc[0] = cc[1] = cc[2] = cc[3] = 0.f;
            }
        }
    }
}

// ---------------- scatter: warp-per-dst segment reduce, fp16 Y ----------------
__global__ void __launch_bounds__(256)
scatter_kernel(const __half* __restrict__ Y, const unsigned* __restrict__ off,
               const int* __restrict__ ssrc, float* __restrict__ OUT) {
    int node = blockIdx.x * 8 + (threadIdx.x >> 5);
    if (node >= NN) return;
    int lane = threadIdx.x & 31;

    unsigned ov = (lane < 9) ? __ldg(off + (size_t)node * 8 + lane) : 0u;
    unsigned onext = __shfl_down_sync(0xffffffffu, ov, 1);
    float invv = 1.0f / fmaxf((float)(onext - ov), 1.0f);
    unsigned o0 = __shfl_sync(0xffffffffu, ov, 0);
    unsigned o8 = __shfl_sync(0xffffffffu, ov, 8);

    float accx = 0.f, accy = 0.f;
    for (unsigned e = o0; e < o8; e += 4) {
        int sa[4];
#pragma unroll
        for (int j = 0; j < 4; j++)
            sa[j] = (e + j < o8) ? __ldg(ssrc + e + j) : -1;
        float2 v[4];
#pragma unroll
        for (int j = 0; j < 4; j++) {
            v[j] = make_float2(0.f, 0.f);
            if (sa[j] >= 0) {
                __half2 hv = *(const __half2*)(Y + (size_t)sa[j] * 64 + lane * 2);
                v[j] = __half22float2(hv);
            }
        }
#pragma unroll
        for (int j = 0; j < 4; j++) {
            if (sa[j] >= 0) {
                float iv = __shfl_sync(0xffffffffu, invv, sa[j] & 7);
                accx += v[j].x * iv; accy += v[j].y * iv;
            }
        }
    }
    float2* op = (float2*)(OUT + (size_t)node * 64 + lane * 2);
    float2 cur = *op;
    *op = make_float2(cur.x + accx, cur.y + accy);
}

// ---------------- batch norm ----------------
__global__ void bn_stats(const float* __restrict__ H, float* __restrict__ acc) {
    int ch = threadIdx.x & 63, ry = threadIdx.x >> 6;
    float s = 0.f, q = 0.f;
    for (int r = blockIdx.x * 4 + ry; r < NN; r += gridDim.x * 4) {
        float v = H[(size_t)r * 64 + ch];
        s += v; q += v * v;
    }
    __shared__ float sh[2][4][64];
    sh[0][ry][ch] = s; sh[1][ry][ch] = q;
    __syncthreads();
    if (ry == 0) {
        s = sh[0][0][ch] + sh[0][1][ch] + sh[0][2][ch] + sh[0][3][ch];
        q = sh[1][0][ch] + sh[1][1][ch] + sh[1][2][ch] + sh[1][3][ch];
        atomicAdd(acc + ch, s);
        atomicAdd(acc + 64 + ch, q);
    }
}

__global__ void bn_final(const float* __restrict__ acc, const float* __restrict__ gamma,
                         const float* __restrict__ beta,
                         float* __restrict__ scale, float* __restrict__ shift) {
    int ch = threadIdx.x;
    if (ch >= 64) return;
    const float invN = 1.0f / (float)NN;
    float mu = acc[ch] * invN;
    float var = acc[64 + ch] * invN - mu * mu;
    float sc = gamma[ch] * rsqrtf(var + 1e-5f);
    scale[ch] = sc;
    shift[ch] = beta[ch] - mu * sc;
}

// ---------------- launcher ----------------
extern "C" void kernel_launch(void* const* d_in, const int* in_sizes, int n_in,
                              void* d_out, int out_size) {
    const float* x      = (const float*)d_in[0];
    const int*   ei     = (const int*)d_in[1];
    const int*   etype  = (const int*)d_in[2];
    const float* w1     = (const float*)d_in[3];
    const float* root1  = (const float*)d_in[4];
    const float* b1     = (const float*)d_in[5];
    const float* gamma1 = (const float*)d_in[6];
    const float* beta1  = (const float*)d_in[7];
    const float* w2     = (const float*)d_in[8];
    const float* root2  = (const float*)d_in[9];
    const float* b2     = (const float*)d_in[10];
    float* out = (float*)d_out;

    __half *y;
    float *h, *acc, *scale, *shift;
    unsigned *cnt, *off, *woff, *bsum;
    int *ssrc;
    __nv_bfloat16 *wp1, *wp2;
    cudaGetSymbolAddress((void**)&y, g_y);
    cudaGetSymbolAddress((void**)&h, g_h);
    cudaGetSymbolAddress((void**)&cnt, g_cnt);
    cudaGetSymbolAddress((void**)&off, g_off);
    cudaGetSymbolAddress((void**)&woff, g_woff);
    cudaGetSymbolAddress((void**)&bsum, g_bsum);
    cudaGetSymbolAddress((void**)&ssrc, g_ssrc);
    cudaGetSymbolAddress((void**)&acc, g_acc);
    cudaGetSymbolAddress((void**)&scale, g_scale);
    cudaGetSymbolAddress((void**)&shift, g_shift);
    cudaGetSymbolAddress((void**)&wp1, g_wp1);
    cudaGetSymbolAddress((void**)&wp2, g_wp2);

    cudaFuncSetAttribute(gemm_kernel<false>, cudaFuncAttributeMaxDynamicSharedMemorySize, SMEM_BYTES);
    cudaFuncSetAttribute(gemm_kernel<true>,  cudaFuncAttributeMaxDynamicSharedMemorySize, SMEM_BYTES);

    const int MT = (NN + 63) / 64;             // 1563
    const int NB1 = (NSEG + 2047) / 2048;      // 391

    cudaMemsetAsync(cnt, 0, NSEG * sizeof(unsigned), 0);
    cudaMemsetAsync(acc, 0, 128 * sizeof(float), 0);

    prep_w<<<(9 * 8192 + 255) / 256, 256>>>(w1, root1, wp1);   // 1
    prep_w<<<(9 * 8192 + 255) / 256, 256>>>(w2, root2, wp2);   // 2
    hist_kernel<<<(EE + 255) / 256, 256>>>(ei, etype, cnt);    // 3
    gemm_kernel<false><<<MT, 256, SMEM_BYTES>>>(x, wp1, b1, nullptr, nullptr, y, h); // 4 (profiled)
    scan1<<<NB1, 256>>>(cnt, off, bsum);                       // 5
    scan2<<<1, 512>>>(bsum, NB1);                              // 6
    scan3<<<(NSEG + 255) / 256, 256>>>(off, woff, bsum);       // 7
    sort_kernel<<<(EE + 255) / 256, 256>>>(ei, etype, woff, ssrc); // 8
    scatter_kernel<<<(NN + 7) / 8, 256>>>(y, off, ssrc, h);    // 9
    bn_stats<<<1024, 256>>>(h, acc);                           // 10
    bn_final<<<1, 64>>>(acc, gamma1, beta1, scale, shift);     // 11
    gemm_kernel<true><<<MT, 256, SMEM_BYTES>>>(h, wp2, b2, scale, shift, y, out); // 12
    scatter_kernel<<<(NN + 7) / 8, 256>>>(y, off, ssrc, out);  // 13
}

// round 14
// speedup vs baseline: 1.1445x; 1.0797x over previous
#include <cuda_runtime.h>
#include <cuda_bf16.h>
#include <cuda_fp16.h>
#include <cstdint>

#define NN 100000
#define EE 1600000
#define NSEG (NN * 8)
#define AST 136                 // A smem row stride (bf16): [Ah 64 | Al 64 | pad 8]
#define SMEM_BYTES (64*AST*2)   // 17408 — A only

__device__ __align__(16) __half   g_y[(size_t)NN * 512];
__device__ __align__(16) float    g_h[(size_t)NN * 64];
__device__ __align__(16) unsigned g_cnt[NSEG];
__device__ __align__(16) unsigned g_off[NSEG + 1];
__device__ __align__(16) unsigned g_woff[NSEG];
__device__ __align__(16) unsigned g_bsum[512];
__device__ __align__(16) int      g_ssrc[EE];
__device__ __align__(16) float    g_acc[128];
__device__ __align__(16) float    g_scale[64];
__device__ __align__(16) float    g_shift[64];
// fragment-packed W: [nc 9][ns 4][kt 4][hb 2][lane 32] uint4
__device__ __align__(16) __nv_bfloat16 g_wp1[9 * 8192];
__device__ __align__(16) __nv_bfloat16 g_wp2[9 * 8192];

// ---------------- prep ----------------
__global__ void hist_kernel(const int* __restrict__ ei, const int* __restrict__ et,
                            unsigned* __restrict__ cnt) {
    int e = blockIdx.x * 256 + threadIdx.x;
    if (e >= EE) return;
    atomicAdd(cnt + ei[EE + e] * 8 + et[e], 1u);
}

__global__ void scan1(const unsigned* __restrict__ cnt, unsigned* __restrict__ off,
                      unsigned* __restrict__ bsum) {
    __shared__ unsigned sh[256];
    int t = threadIdx.x;
    int base = blockIdx.x * 2048 + t * 8;
    unsigned v[8], s = 0;
#pragma unroll
    for (int j = 0; j < 8; j++) { v[j] = (base + j < NSEG) ? cnt[base + j] : 0u; s += v[j]; }
    sh[t] = s; __syncthreads();
    for (int d = 1; d < 256; d <<= 1) {
        unsigned x = (t >= d) ? sh[t - d] : 0u;
        __syncthreads(); sh[t] += x; __syncthreads();
    }
    if (t == 255) bsum[blockIdx.x] = sh[255];
    unsigned run = sh[t] - s;
#pragma unroll
    for (int j = 0; j < 8; j++)
        if (base + j < NSEG) { off[base + j] = run; run += v[j]; }
}

__global__ void scan2(unsigned* bsum, int nb) {
    __shared__ unsigned sh[512];
    int t = threadIdx.x;
    unsigned v = (t < nb) ? bsum[t] : 0u;
    sh[t] = v; __syncthreads();
    for (int d = 1; d < 512; d <<= 1) {
        unsigned x = (t >= d) ? sh[t - d] : 0u;
        __syncthreads(); sh[t] += x; __syncthreads();
    }
    if (t < nb) bsum[t] = sh[t] - v;
}

__global__ void scan3(unsigned* __restrict__ off, unsigned* __restrict__ woff,
                      const unsigned* __restrict__ bsum) {
    int i = blockIdx.x * 256 + threadIdx.x;
    if (i < NSEG) { unsigned o = off[i] + bsum[i >> 11]; off[i] = o; woff[i] = o; }
    if (i == 0) off[NSEG] = EE;
}

__global__ void sort_kernel(const int* __restrict__ ei, const int* __restrict__ et,
                            unsigned* __restrict__ woff, int* __restrict__ ssrc) {
    int e = blockIdx.x * 256 + threadIdx.x;
    if (e >= EE) return;
    int r = et[e];
    int b = ei[EE + e] * 8 + r;
    unsigned pos = atomicAdd(woff + b, 1u);
    ssrc[pos] = ei[e] * 8 + r;
}

// fragment-pack W (+root as rel 8); elem idx: ((((nc*4+ns)*4+kt)*2+hb)*32 + lane)*8 + r*2 + p
__global__ void prep_w(const float* __restrict__ w, const float* __restrict__ root,
                       __nv_bfloat16* __restrict__ wp) {
    int i = blockIdx.x * 256 + threadIdx.x;
    if (i >= 9 * 8192) return;
    int nc = i >> 13;
    int rem = i & 8191;
    int ns = rem >> 11;
    int rem2 = rem & 2047;
    int kt = rem2 >> 9;
    int rem3 = rem2 & 511;
    int hb = rem3 >> 8;
    int rem4 = rem3 & 255;
    int lane = rem4 >> 3;
    int q = rem4 & 7;
    int r = q >> 1, p = q & 1;
    int n_local = ns * 16 + (r >> 1) * 8 + (lane >> 2);
    int j = nc * 64 + n_local;
    int k = kt * 16 + (lane & 3) * 2 + (r & 1) * 8 + p;
    int rel = j >> 6, o = j & 63;
    float v = (rel < 8) ? w[((size_t)rel * 64 + k) * 64 + o] : root[(size_t)k * 64 + o];
    __nv_bfloat16 hi = __float2bfloat16(v);
    wp[i] = (hb == 0) ? hi : __float2bfloat16(v - __bfloat162float(hi));
}

// ---------------- GEMM: barrier-free, kt-pipelined B prefetch ----------------
__device__ __forceinline__ uint32_t smem_u32(const void* p) {
    uint32_t a;
    asm("{ .reg .u64 t; cvta.to.shared.u64 t, %1; cvt.u32.u64 %0, t; }" : "=r"(a) : "l"(p));
    return a;
}
__device__ __forceinline__ void ldsm4(unsigned& r0, unsigned& r1, unsigned& r2, unsigned& r3,
                                      uint32_t addr) {
    asm volatile("ldmatrix.sync.aligned.m8n8.x4.shared.b16 {%0,%1,%2,%3}, [%4];"
                 : "=r"(r0), "=r"(r1), "=r"(r2), "=r"(r3) : "r"(addr));
}

#define MMA16816(c0,c1,c2,c3,a0,a1,a2,a3,b0,b1)                                     \
    asm volatile("mma.sync.aligned.m16n8k16.row.col.f32.bf16.bf16.f32 "             \
                 "{%0,%1,%2,%3},{%4,%5,%6,%7},{%8,%9},{%0,%1,%2,%3};"               \
                 : "+f"(c0), "+f"(c1), "+f"(c2), "+f"(c3)                           \
                 : "r"(a0), "r"(a1), "r"(a2), "r"(a3), "r"(b0), "r"(b1))

template <bool APPLY_BN>
__global__ void __launch_bounds__(256, 2)
gemm_kernel(const float* __restrict__ X, const __nv_bfloat16* __restrict__ WP,
            const float* __restrict__ bias,
            const float* __restrict__ bnscale, const float* __restrict__ bnshift,
            __half* __restrict__ Y, float* __restrict__ OUT) {
    extern __shared__ char smem[];
    __nv_bfloat16* As = (__nv_bfloat16*)smem;          // [64][AST]

    const int tid = threadIdx.x;
    const int wid = tid >> 5, lane = tid & 31;
    const int g = lane >> 2, tig = lane & 3;
    const int warpM = wid & 1, ns = wid >> 1;          // m32 x n16 warp tiles
    const int mbase = blockIdx.x * 64;
    const int mat = lane >> 3, rl = lane & 7;

    // A fill: 64 rows x 32 float2
    for (int it = tid; it < 64 * 32; it += 256) {
        int row = it >> 5, dp = it & 31;
        int grow = mbase + row;
        float2 v = make_float2(0.f, 0.f);
        if (grow < NN) v = *(const float2*)(X + (size_t)grow * 64 + dp * 2);
        if (APPLY_BN) {
            v.x = fmaxf(v.x * bnscale[dp * 2]     + bnshift[dp * 2], 0.f);
            v.y = fmaxf(v.y * bnscale[dp * 2 + 1] + bnshift[dp * 2 + 1], 0.f);
        }
        __nv_bfloat162 hi, lo;
        hi.x = __float2bfloat16(v.x); hi.y = __float2bfloat16(v.y);
        lo.x = __float2bfloat16(v.x - __bfloat162float(hi.x));
        lo.y = __float2bfloat16(v.y - __bfloat162float(hi.y));
        __nv_bfloat162* arow = (__nv_bfloat162*)(As + row * AST);
        arow[dp] = hi; arow[32 + dp] = lo;
    }
    __syncthreads();    // the ONLY block barrier

    // A frags -> registers once via ldmatrix
    const uint32_t as_u = smem_u32(As);
    unsigned ah[2][4][4], al[2][4][4];
#pragma unroll
    for (int mt = 0; mt < 2; mt++) {
#pragma unroll
        for (int kt = 0; kt < 4; kt++) {
            uint32_t row = warpM * 32 + mt * 16 + (mat & 1) * 8 + rl;
            uint32_t kc  = kt * 16 + (mat >> 1) * 8;
            uint32_t ad = as_u + (row * AST + kc) * 2;
            ldsm4(ah[mt][kt][0], ah[mt][kt][1], ah[mt][kt][2], ah[mt][kt][3], ad);
            ldsm4(al[mt][kt][0], al[mt][kt][1], al[mt][kt][2], al[mt][kt][3], ad + 128);
        }
    }

    float c[2][2][4];
#pragma unroll
    for (int mt = 0; mt < 2; mt++)
#pragma unroll
        for (int nt = 0; nt < 2; nt++)
#pragma unroll
            for (int k = 0; k < 4; k++) c[mt][nt][k] = 0.f;

    // B frag address base (uint4 units): nc*1024 + ns*256 + kt*64 + hb*32 + lane
    const uint4* wb = (const uint4*)WP + ns * 256 + lane;

    uint4 bh = __ldg(wb);            // (0,0,hi)
    uint4 bl = __ldg(wb + 32);       // (0,0,lo)

#pragma unroll 1
    for (int nc = 0; nc < 9; nc++) {
#pragma unroll
        for (int kt = 0; kt < 4; kt++) {
            // prefetch next kt-step (wraps to next chunk; clamp at end)
            int nn = (kt == 3) ? nc + 1 : nc;
            if (nn > 8) nn = 8;
            int nk = (kt + 1) & 3;
            const uint4* np = wb + nn * 1024 + nk * 64;
            uint4 nbh = __ldg(np);
            uint4 nbl = __ldg(np + 32);

#pragma unroll
            for (int mt = 0; mt < 2; mt++) {
                MMA16816(c[mt][0][0], c[mt][0][1], c[mt][0][2], c[mt][0][3],
                         ah[mt][kt][0], ah[mt][kt][1], ah[mt][kt][2], ah[mt][kt][3],
                         bh.x, bh.y);
                MMA16816(c[mt][1][0], c[mt][1][1], c[mt][1][2], c[mt][1][3],
                         ah[mt][kt][0], ah[mt][kt][1], ah[mt][kt][2], ah[mt][kt][3],
                         bh.z, bh.w);
                MMA16816(c[mt][0][0], c[mt][0][1], c[mt][0][2], c[mt][0][3],
                         al[mt][kt][0], al[mt][kt][1], al[mt][kt][2], al[mt][kt][3],
                         bh.x, bh.y);
                MMA16816(c[mt][1][0], c[mt][1][1], c[mt][1][2], c[mt][1][3],
                         al[mt][kt][0], al[mt][kt][1], al[mt][kt][2], al[mt][kt][3],
                         bh.z, bh.w);
                MMA16816(c[mt][0][0], c[mt][0][1], c[mt][0][2], c[mt][0][3],
                         ah[mt][kt][0], ah[mt][kt][1], ah[mt][kt][2], ah[mt][kt][3],
                         bl.x, bl.y);
                MMA16816(c[mt][1][0], c[mt][1][1], c[mt][1][2], c[mt][1][3],
                         ah[mt][kt][0], ah[mt][kt][1], ah[mt][kt][2], ah[mt][kt][3],
                         bl.z, bl.w);
            }
            bh = nbh; bl = nbl;
        }

        // epilogue for this 64-col chunk (private C regs, no barrier)
#pragma unroll
        for (int mt = 0; mt < 2; mt++) {
            int row = mbase + warpM * 32 + mt * 16 + g;
#pragma unroll
            for (int nt = 0; nt < 2; nt++) {
                int col = ns * 16 + nt * 8 + 2 * tig;
                float* cc = c[mt][nt];
                if (nc < 8) {
                    size_t base = (size_t)row * 512 + nc * 64 + col;
                    if (row < NN)
                        *(__half2*)(Y + base) = __floats2half2_rn(cc[0], cc[1]);
                    if (row + 8 < NN)
                        *(__half2*)(Y + base + 8 * 512) = __floats2half2_rn(cc[2], cc[3]);
                } else {
                    float2 bb = *(const float2*)(bias + col);
                    if (row < NN)
                        *(float2*)(OUT + (size_t)row * 64 + col) = make_float2(cc[0] + bb.x, cc[1] + bb.y);
                    if (row + 8 < NN)
                        *(float2*)(OUT + (size_t)(row + 8) * 64 + col) = make_float2(cc[2] + bb.x, cc[3] + bb.y);
                }
                cc[0] = cc[1] = cc[2] = cc[3] = 0.f;
            }
        }
    }
}

// ---------------- scatter: warp-per-dst segment reduce, fp16 Y ----------------
__global__ void __launch_bounds__(256)
scatter_kernel(const __half* __restrict__ Y, const unsigned* __restrict__ off,
               const int* __restrict__ ssrc, float* __restrict__ OUT) {
    int node = blockIdx.x * 8 + (threadIdx.x >> 5);
    if (node >= NN) return;
    int lane = threadIdx.x & 31;

    unsigned ov = (lane < 9) ? __ldg(off + (size_t)node * 8 + lane) : 0u;
    unsigned onext = __shfl_down_sync(0xffffffffu, ov, 1);
    float invv = 1.0f / fmaxf((float)(onext - ov), 1.0f);
    unsigned o0 = __shfl_sync(0xffffffffu, ov, 0);
    unsigned o8 = __shfl_sync(0xffffffffu, ov, 8);

    float accx = 0.f, accy = 0.f;
    for (unsigned e = o0; e < o8; e += 4) {
        int sa[4];
#pragma unroll
        for (int j = 0; j < 4; j++)
            sa[j] = (e + j < o8) ? __ldg(ssrc + e + j) : -1;
        float2 v[4];
#pragma unroll
        for (int j = 0; j < 4; j++) {
            v[j] = make_float2(0.f, 0.f);
            if (sa[j] >= 0) {
                __half2 hv = *(const __half2*)(Y + (size_t)sa[j] * 64 + lane * 2);
                v[j] = __half22float2(hv);
            }
        }
#pragma unroll
        for (int j = 0; j < 4; j++) {
            if (sa[j] >= 0) {
                float iv = __shfl_sync(0xffffffffu, invv, sa[j] & 7);
                accx += v[j].x * iv; accy += v[j].y * iv;
            }
        }
    }
    float2* op = (float2*)(OUT + (size_t)node * 64 + lane * 2);
    float2 cur = *op;
    *op = make_float2(cur.x + accx, cur.y + accy);
}

// ---------------- batch norm ----------------
__global__ void bn_stats(const float* __restrict__ H, float* __restrict__ acc) {
    int ch = threadIdx.x & 63, ry = threadIdx.x >> 6;
    float s = 0.f, q = 0.f;
    for (int r = blockIdx.x * 4 + ry; r < NN; r += gridDim.x * 4) {
        float v = H[(size_t)r * 64 + ch];
        s += v; q += v * v;
    }
    __shared__ float sh[2][4][64];
    sh[0][ry][ch] = s; sh[1][ry][ch] = q;
    __syncthreads();
    if (ry == 0) {
        s = sh[0][0][ch] + sh[0][1][ch] + sh[0][2][ch] + sh[0][3][ch];
        q = sh[1][0][ch] + sh[1][1][ch] + sh[1][2][ch] + sh[1][3][ch];
        atomicAdd(acc + ch, s);
        atomicAdd(acc + 64 + ch, q);
    }
}

__global__ void bn_final(const float* __restrict__ acc, const float* __restrict__ gamma,
                         const float* __restrict__ beta,
                         float* __restrict__ scale, float* __restrict__ shift) {
    int ch = threadIdx.x;
    if (ch >= 64) return;
    const float invN = 1.0f / (float)NN;
    float mu = acc[ch] * invN;
    float var = acc[64 + ch] * invN - mu * mu;
    float sc = gamma[ch] * rsqrtf(var + 1e-5f);
    scale[ch] = sc;
    shift[ch] = beta[ch] - mu * sc;
}

// ---------------- launcher: fork sort pipeline onto a second stream ----------------
extern "C" void kernel_launch(void* const* d_in, const int* in_sizes, int n_in,
                              void* d_out, int out_size) {
    const float* x      = (const float*)d_in[0];
    const int*   ei     = (const int*)d_in[1];
    const int*   etype  = (const int*)d_in[2];
    const float* w1     = (const float*)d_in[3];
    const float* root1  = (const float*)d_in[4];
    const float* b1     = (const float*)d_in[5];
    const float* gamma1 = (const float*)d_in[6];
    const float* beta1  = (const float*)d_in[7];
    const float* w2     = (const float*)d_in[8];
    const float* root2  = (const float*)d_in[9];
    const float* b2     = (const float*)d_in[10];
    float* out = (float*)d_out;

    __half *y;
    float *h, *acc, *scale, *shift;
    unsigned *cnt, *off, *woff, *bsum;
    int *ssrc;
    __nv_bfloat16 *wp1, *wp2;
    cudaGetSymbolAddress((void**)&y, g_y);
    cudaGetSymbolAddress((void**)&h, g_h);
    cudaGetSymbolAddress((void**)&cnt, g_cnt);
    cudaGetSymbolAddress((void**)&off, g_off);
    cudaGetSymbolAddress((void**)&woff, g_woff);
    cudaGetSymbolAddress((void**)&bsum, g_bsum);
    cudaGetSymbolAddress((void**)&ssrc, g_ssrc);
    cudaGetSymbolAddress((void**)&acc, g_acc);
    cudaGetSymbolAddress((void**)&scale, g_scale);
    cudaGetSymbolAddress((void**)&shift, g_shift);
    cudaGetSymbolAddress((void**)&wp1, g_wp1);
    cudaGetSymbolAddress((void**)&wp2, g_wp2);

    cudaFuncSetAttribute(gemm_kernel<false>, cudaFuncAttributeMaxDynamicSharedMemorySize, SMEM_BYTES);
    cudaFuncSetAttribute(gemm_kernel<true>,  cudaFuncAttributeMaxDynamicSharedMemorySize, SMEM_BYTES);

    static cudaStream_t s2 = nullptr;
    static cudaEvent_t evFork = nullptr, evJoin = nullptr;
    if (!s2) {
        cudaStreamCreate(&s2);
        cudaEventCreateWithFlags(&evFork, cudaEventDisableTiming);
        cudaEventCreateWithFlags(&evJoin, cudaEventDisableTiming);
    }

    const int MT = (NN + 63) / 64;             // 1563
    const int NB1 = (NSEG + 2047) / 2048;      // 391

    cudaMemsetAsync(acc, 0, 128 * sizeof(float), 0);

    prep_w<<<(9 * 8192 + 255) / 256, 256>>>(w1, root1, wp1);           // #1 (stream 0)
    prep_w<<<(9 * 8192 + 255) / 256, 256>>>(w2, root2, wp2);           // #2

    // fork: sort pipeline on s2
    cudaEventRecord(evFork, 0);
    cudaStreamWaitEvent(s2, evFork, 0);
    cudaMemsetAsync(cnt, 0, NSEG * sizeof(unsigned), s2);
    hist_kernel<<<(EE + 255) / 256, 256, 0, s2>>>(ei, etype, cnt);     // #3

    gemm_kernel<false><<<MT, 256, SMEM_BYTES>>>(x, wp1, b1, nullptr, nullptr, y, h); // #4 (profiled)

    scan1<<<NB1, 256, 0, s2>>>(cnt, off, bsum);                        // #5
    scan2<<<1, 512, 0, s2>>>(bsum, NB1);                               // #6
    scan3<<<(NSEG + 255) / 256, 256, 0, s2>>>(off, woff, bsum);        // #7
    sort_kernel<<<(EE + 255) / 256, 256, 0, s2>>>(ei, etype, woff, ssrc); // #8
    cudaEventRecord(evJoin, s2);
    cudaStreamWaitEvent(0, evJoin, 0);

    scatter_kernel<<<(NN + 7) / 8, 256>>>(y, off, ssrc, h);            // #9
    bn_stats<<<1024, 256>>>(h, acc);                                   // #10
    bn_final<<<1, 64>>>(acc, gamma1, beta1, scale, shift);             // #11
    gemm_kernel<true><<<MT, 256, SMEM_BYTES>>>(h, wp2, b2, scale, shift, y, out); // #12
    scatter_kernel<<<(NN + 7) / 8, 256>>>(y, off, ssrc, out);          // #13
}

// round 15
// speedup vs baseline: 1.1916x; 1.0412x over previous
#include <cuda_runtime.h>
#include <cuda_bf16.h>
#include <cuda_fp16.h>
#include <cstdint>

#define NN 100000
#define EE 1600000
#define NSEG (NN * 8)
#define AST 136                 // A smem row stride (half): [Xh 64 | Xl 64 | pad 8]
#define SMEM_BYTES (64*AST*2)   // 17408

__device__ __align__(16) __half   g_y[(size_t)NN * 512];
__device__ __align__(16) float    g_h[(size_t)NN * 64];
__device__ __align__(16) unsigned g_cnt[NSEG];
__device__ __align__(16) unsigned g_off[NSEG + 1];
__device__ __align__(16) unsigned g_woff[NSEG];
__device__ __align__(16) unsigned g_bsum[512];
__device__ __align__(16) int      g_ssrc[EE];
__device__ __align__(16) float    g_acc[128];
__device__ __align__(16) float    g_scale[64];
__device__ __align__(16) float    g_shift[64];
// fragment-packed W (fp16, hi only): [nc 9][ns 4][kt 4][lane 32] uint4
__device__ __align__(16) __half g_wp1[9 * 4096];
__device__ __align__(16) __half g_wp2[9 * 4096];

// ---------------- prep ----------------
__global__ void hist_kernel(const int* __restrict__ ei, const int* __restrict__ et,
                            unsigned* __restrict__ cnt) {
    int e = blockIdx.x * 256 + threadIdx.x;
    if (e >= EE) return;
    atomicAdd(cnt + ei[EE + e] * 8 + et[e], 1u);
}

__global__ void scan1(const unsigned* __restrict__ cnt, unsigned* __restrict__ off,
                      unsigned* __restrict__ bsum) {
    __shared__ unsigned sh[256];
    int t = threadIdx.x;
    int base = blockIdx.x * 2048 + t * 8;
    unsigned v[8], s = 0;
#pragma unroll
    for (int j = 0; j < 8; j++) { v[j] = (base + j < NSEG) ? cnt[base + j] : 0u; s += v[j]; }
    sh[t] = s; __syncthreads();
    for (int d = 1; d < 256; d <<= 1) {
        unsigned x = (t >= d) ? sh[t - d] : 0u;
        __syncthreads(); sh[t] += x; __syncthreads();
    }
    if (t == 255) bsum[blockIdx.x] = sh[255];
    unsigned run = sh[t] - s;
#pragma unroll
    for (int j = 0; j < 8; j++)
        if (base + j < NSEG) { off[base + j] = run; run += v[j]; }
}

__global__ void scan2(unsigned* bsum, int nb) {
    __shared__ unsigned sh[512];
    int t = threadIdx.x;
    unsigned v = (t < nb) ? bsum[t] : 0u;
    sh[t] = v; __syncthreads();
    for (int d = 1; d < 512; d <<= 1) {
        unsigned x = (t >= d) ? sh[t - d] : 0u;
        __syncthreads(); sh[t] += x; __syncthreads();
    }
    if (t < nb) bsum[t] = sh[t] - v;
}

__global__ void scan3(unsigned* __restrict__ off, unsigned* __restrict__ woff,
                      const unsigned* __restrict__ bsum) {
    int i = blockIdx.x * 256 + threadIdx.x;
    if (i < NSEG) { unsigned o = off[i] + bsum[i >> 11]; off[i] = o; woff[i] = o; }
    if (i == 0) off[NSEG] = EE;
}

__global__ void sort_kernel(const int* __restrict__ ei, const int* __restrict__ et,
                            unsigned* __restrict__ woff, int* __restrict__ ssrc) {
    int e = blockIdx.x * 256 + threadIdx.x;
    if (e >= EE) return;
    int r = et[e];
    int b = ei[EE + e] * 8 + r;
    unsigned pos = atomicAdd(woff + b, 1u);
    ssrc[pos] = ei[e] * 8 + r;
}

// fragment-pack W (+root as rel 8), fp16 hi only.
// elem idx: (((nc*4+ns)*4+kt)*32 + lane)*8 + r*2 + p
__global__ void prep_w(const float* __restrict__ w, const float* __restrict__ root,
                       __half* __restrict__ wp) {
    int i = blockIdx.x * 256 + threadIdx.x;
    if (i >= 9 * 4096) return;
    int nc = i >> 12;
    int rem = i & 4095;
    int ns = rem >> 10;
    int rem2 = rem & 1023;
    int kt = rem2 >> 8;
    int rem3 = rem2 & 255;
    int lane = rem3 >> 3;
    int q = rem3 & 7;
    int r = q >> 1, p = q & 1;
    int n_local = ns * 16 + (r >> 1) * 8 + (lane >> 2);
    int j = nc * 64 + n_local;
    int k = kt * 16 + (lane & 3) * 2 + (r & 1) * 8 + p;
    int rel = j >> 6, o = j & 63;
    float v = (rel < 8) ? w[((size_t)rel * 64 + k) * 64 + o] : root[(size_t)k * 64 + o];
    wp[i] = __float2half(v);
}

// ---------------- GEMM: barrier-free, fp16 2-term, kt-pipelined ----------------
__device__ __forceinline__ uint32_t smem_u32(const void* p) {
    uint32_t a;
    asm("{ .reg .u64 t; cvta.to.shared.u64 t, %1; cvt.u32.u64 %0, t; }" : "=r"(a) : "l"(p));
    return a;
}
__device__ __forceinline__ void ldsm4(unsigned& r0, unsigned& r1, unsigned& r2, unsigned& r3,
                                      uint32_t addr) {
    asm volatile("ldmatrix.sync.aligned.m8n8.x4.shared.b16 {%0,%1,%2,%3}, [%4];"
                 : "=r"(r0), "=r"(r1), "=r"(r2), "=r"(r3) : "r"(addr));
}

#define MMAF16(c0,c1,c2,c3,a0,a1,a2,a3,b0,b1)                                       \
    asm volatile("mma.sync.aligned.m16n8k16.row.col.f32.f16.f16.f32 "               \
                 "{%0,%1,%2,%3},{%4,%5,%6,%7},{%8,%9},{%0,%1,%2,%3};"               \
                 : "+f"(c0), "+f"(c1), "+f"(c2), "+f"(c3)                           \
                 : "r"(a0), "r"(a1), "r"(a2), "r"(a3), "r"(b0), "r"(b1))

template <bool APPLY_BN>
__global__ void __launch_bounds__(256, 2)
gemm_kernel(const float* __restrict__ X, const __half* __restrict__ WP,
            const float* __restrict__ bias,
            const float* __restrict__ bnscale, const float* __restrict__ bnshift,
            __half* __restrict__ Y, float* __restrict__ OUT) {
    extern __shared__ char smem[];
    __half* As = (__half*)smem;          // [64][AST]

    const int tid = threadIdx.x;
    const int wid = tid >> 5, lane = tid & 31;
    const int g = lane >> 2, tig = lane & 3;
    const int warpM = wid & 1, ns = wid >> 1;          // m32 x n16 warp tiles
    const int mbase = blockIdx.x * 64;
    const int mat = lane >> 3, rl = lane & 7;

    // A fill: 64 rows x 32 float2 -> fp16 hi/lo
    for (int it = tid; it < 64 * 32; it += 256) {
        int row = it >> 5, dp = it & 31;
        int grow = mbase + row;
        float2 v = make_float2(0.f, 0.f);
        if (grow < NN) v = *(const float2*)(X + (size_t)grow * 64 + dp * 2);
        if (APPLY_BN) {
            v.x = fmaxf(v.x * bnscale[dp * 2]     + bnshift[dp * 2], 0.f);
            v.y = fmaxf(v.y * bnscale[dp * 2 + 1] + bnshift[dp * 2 + 1], 0.f);
        }
        __half2 hi, lo;
        hi.x = __float2half(v.x); hi.y = __float2half(v.y);
        lo.x = __float2half(v.x - __half2float(hi.x));
        lo.y = __float2half(v.y - __half2float(hi.y));
        __half2* arow = (__half2*)(As + row * AST);
        arow[dp] = hi; arow[32 + dp] = lo;
    }
    __syncthreads();    // the ONLY block barrier

    // A frags -> registers once via ldmatrix
    const uint32_t as_u = smem_u32(As);
    unsigned ah[2][4][4], al[2][4][4];
#pragma unroll
    for (int mt = 0; mt < 2; mt++) {
#pragma unroll
        for (int kt = 0; kt < 4; kt++) {
            uint32_t row = warpM * 32 + mt * 16 + (mat & 1) * 8 + rl;
            uint32_t kc  = kt * 16 + (mat >> 1) * 8;
            uint32_t ad = as_u + (row * AST + kc) * 2;
            ldsm4(ah[mt][kt][0], ah[mt][kt][1], ah[mt][kt][2], ah[mt][kt][3], ad);
            ldsm4(al[mt][kt][0], al[mt][kt][1], al[mt][kt][2], al[mt][kt][3], ad + 128);
        }
    }

    float c[2][2][4];
#pragma unroll
    for (int mt = 0; mt < 2; mt++)
#pragma unroll
        for (int nt = 0; nt < 2; nt++)
#pragma unroll
            for (int k = 0; k < 4; k++) c[mt][nt][k] = 0.f;

    // B frag base (uint4 units): nc*512 + ns*128 + kt*32 + lane
    const uint4* wb = (const uint4*)WP + ns * 128 + lane;
    uint4 bh = __ldg(wb);            // (nc0, kt0)

#pragma unroll 1
    for (int nc = 0; nc < 9; nc++) {
#pragma unroll
        for (int kt = 0; kt < 4; kt++) {
            // prefetch next kt-step (wraps to next chunk; clamp at end)
            int nn = (kt == 3) ? nc + 1 : nc;
            if (nn > 8) nn = 8;
            int nk = (kt + 1) & 3;
            uint4 nbh = __ldg(wb + nn * 512 + nk * 32);

#pragma unroll
            for (int mt = 0; mt < 2; mt++) {
                MMAF16(c[mt][0][0], c[mt][0][1], c[mt][0][2], c[mt][0][3],
                       ah[mt][kt][0], ah[mt][kt][1], ah[mt][kt][2], ah[mt][kt][3],
                       bh.x, bh.y);
                MMAF16(c[mt][1][0], c[mt][1][1], c[mt][1][2], c[mt][1][3],
                       ah[mt][kt][0], ah[mt][kt][1], ah[mt][kt][2], ah[mt][kt][3],
                       bh.z, bh.w);
                MMAF16(c[mt][0][0], c[mt][0][1], c[mt][0][2], c[mt][0][3],
                       al[mt][kt][0], al[mt][kt][1], al[mt][kt][2], al[mt][kt][3],
                       bh.x, bh.y);
                MMAF16(c[mt][1][0], c[mt][1][1], c[mt][1][2], c[mt][1][3],
                       al[mt][kt][0], al[mt][kt][1], al[mt][kt][2], al[mt][kt][3],
                       bh.z, bh.w);
            }
            bh = nbh;
        }

        // epilogue for this 64-col chunk
#pragma unroll
        for (int mt = 0; mt < 2; mt++) {
            int row = mbase + warpM * 32 + mt * 16 + g;
#pragma unroll
            for (int nt = 0; nt < 2; nt++) {
                int col = ns * 16 + nt * 8 + 2 * tig;
                float* cc = c[mt][nt];
                if (nc < 8) {
                    size_t base = (size_t)row * 512 + nc * 64 + col;
                    if (row < NN)
                        *(__half2*)(Y + base) = __floats2half2_rn(cc[0], cc[1]);
                    if (row + 8 < NN)
                        *(__half2*)(Y + base + 8 * 512) = __floats2half2_rn(cc[2], cc[3]);
                } else {
                    float2 bb = *(const float2*)(bias + col);
                    if (row < NN)
                        *(float2*)(OUT + (size_t)row * 64 + col) = make_float2(cc[0] + bb.x, cc[1] + bb.y);
                    if (row + 8 < NN)
                        *(float2*)(OUT + (size_t)(row + 8) * 64 + col) = make_float2(cc[2] + bb.x, cc[3] + bb.y);
                }
                cc[0] = cc[1] = cc[2] = cc[3] = 0.f;
            }
        }
    }
}

// ---------------- scatter: warp-per-dst segment reduce, fp16 Y ----------------
__global__ void __launch_bounds__(256)
scatter_kernel(const __half* __restrict__ Y, const unsigned* __restrict__ off,
               const int* __restrict__ ssrc, float* __restrict__ OUT) {
    int node = blockIdx.x * 8 + (threadIdx.x >> 5);
    if (node >= NN) return;
    int lane = threadIdx.x & 31;

    unsigned ov = (lane < 9) ? __ldg(off + (size_t)node * 8 + lane) : 0u;
    unsigned onext = __shfl_down_sync(0xffffffffu, ov, 1);
    float invv = 1.0f / fmaxf((float)(onext - ov), 1.0f);
    unsigned o0 = __shfl_sync(0xffffffffu, ov, 0);
    unsigned o8 = __shfl_sync(0xffffffffu, ov, 8);

    float accx = 0.f, accy = 0.f;
    for (unsigned e = o0; e < o8; e += 4) {
        int sa[4];
#pragma unroll
        for (int j = 0; j < 4; j++)
            sa[j] = (e + j < o8) ? __ldg(ssrc + e + j) : -1;
        float2 v[4];
#pragma unroll
        for (int j = 0; j < 4; j++) {
            v[j] = make_float2(0.f, 0.f);
            if (sa[j] >= 0) {
                __half2 hv = *(const __half2*)(Y + (size_t)sa[j] * 64 + lane * 2);
                v[j] = __half22float2(hv);
            }
        }
#pragma unroll
        for (int j = 0; j < 4; j++) {
            if (sa[j] >= 0) {
                float iv = __shfl_sync(0xffffffffu, invv, sa[j] & 7);
                accx += v[j].x * iv; accy += v[j].y * iv;
            }
        }
    }
    float2* op = (float2*)(OUT + (size_t)node * 64 + lane * 2);
    float2 cur = *op;
    *op = make_float2(cur.x + accx, cur.y + accy);
}

// ---------------- batch norm ----------------
__global__ void bn_stats(const float* __restrict__ H, float* __restrict__ acc) {
    int ch = threadIdx.x & 63, ry = threadIdx.x >> 6;
    float s = 0.f, q = 0.f;
    for (int r = blockIdx.x * 4 + ry; r < NN; r += gridDim.x * 4) {
        float v = H[(size_t)r * 64 + ch];
        s += v; q += v * v;
    }
    __shared__ float sh[2][4][64];
    sh[0][ry][ch] = s; sh[1][ry][ch] = q;
    __syncthreads();
    if (ry == 0) {
        s = sh[0][0][ch] + sh[0][1][ch] + sh[0][2][ch] + sh[0][3][ch];
        q = sh[1][0][ch] + sh[1][1][ch] + sh[1][2][ch] + sh[1][3][ch];
        atomicAdd(acc + ch, s);
        atomicAdd(acc + 64 + ch, q);
    }
}

__global__ void bn_final(const float* __restrict__ acc, const float* __restrict__ gamma,
                         const float* __restrict__ beta,
                         float* __restrict__ scale, float* __restrict__ shift) {
    int ch = threadIdx.x;
    if (ch >= 64) return;
    const float invN = 1.0f / (float)NN;
    float mu = acc[ch] * invN;
    float var = acc[64 + ch] * invN - mu * mu;
    float sc = gamma[ch] * rsqrtf(var + 1e-5f);
    scale[ch] = sc;
    shift[ch] = beta[ch] - mu * sc;
}

// ---------------- launcher ----------------
extern "C" void kernel_launch(void* const* d_in, const int* in_sizes, int n_in,
                              void* d_out, int out_size) {
    const float* x      = (const float*)d_in[0];
    const int*   ei     = (const int*)d_in[1];
    const int*   etype  = (const int*)d_in[2];
    const float* w1     = (const float*)d_in[3];
    const float* root1  = (const float*)d_in[4];
    const float* b1     = (const float*)d_in[5];
    const float* gamma1 = (const float*)d_in[6];
    const float* beta1  = (const float*)d_in[7];
    const float* w2     = (const float*)d_in[8];
    const float* root2  = (const float*)d_in[9];
    const float* b2     = (const float*)d_in[10];
    float* out = (float*)d_out;

    __half *y;
    float *h, *acc, *scale, *shift;
    unsigned *cnt, *off, *woff, *bsum;
    int *ssrc;
    __half *wp1, *wp2;
    cudaGetSymbolAddress((void**)&y, g_y);
    cudaGetSymbolAddress((void**)&h, g_h);
    cudaGetSymbolAddress((void**)&cnt, g_cnt);
    cudaGetSymbolAddress((void**)&off, g_off);
    cudaGetSymbolAddress((void**)&woff, g_woff);
    cudaGetSymbolAddress((void**)&bsum, g_bsum);
    cudaGetSymbolAddress((void**)&ssrc, g_ssrc);
    cudaGetSymbolAddress((void**)&acc, g_acc);
    cudaGetSymbolAddress((void**)&scale, g_scale);
    cudaGetSymbolAddress((void**)&shift, g_shift);
    cudaGetSymbolAddress((void**)&wp1, g_wp1);
    cudaGetSymbolAddress((void**)&wp2, g_wp2);

    cudaFuncSetAttribute(gemm_kernel<false>, cudaFuncAttributeMaxDynamicSharedMemorySize, SMEM_BYTES);
    cudaFuncSetAttribute(gemm_kernel<true>,  cudaFuncAttributeMaxDynamicSharedMemorySize, SMEM_BYTES);

    static cudaStream_t s2 = nullptr;
    static cudaEvent_t evFork = nullptr, evJoin = nullptr;
    if (!s2) {
        cudaStreamCreate(&s2);
        cudaEventCreateWithFlags(&evFork, cudaEventDisableTiming);
        cudaEventCreateWithFlags(&evJoin, cudaEventDisableTiming);
    }

    const int MT = (NN + 63) / 64;             // 1563
    const int NB1 = (NSEG + 2047) / 2048;      // 391
    const int WPN = (9 * 4096 + 255) / 256;    // 144

    cudaMemsetAsync(acc, 0, 128 * sizeof(float), 0);

    prep_w<<<WPN, 256>>>(w1, root1, wp1);                              // #1 (s0)

    // fork: prep_w2 + sort pipeline on s2 (overlap gemm1)
    cudaEventRecord(evFork, 0);
    cudaStreamWaitEvent(s2, evFork, 0);
    cudaMemsetAsync(cnt, 0, NSEG * sizeof(unsigned), s2);
    prep_w<<<WPN, 256, 0, s2>>>(w2, root2, wp2);                       // #2 (s2)
    hist_kernel<<<(EE + 255) / 256, 256, 0, s2>>>(ei, etype, cnt);     // #3 (s2)

    gemm_kernel<false><<<MT, 256, SMEM_BYTES>>>(x, wp1, b1, nullptr, nullptr, y, h); // #4 (profiled)

    scan1<<<NB1, 256, 0, s2>>>(cnt, off, bsum);                        // #5
    scan2<<<1, 512, 0, s2>>>(bsum, NB1);                               // #6
    scan3<<<(NSEG + 255) / 256, 256, 0, s2>>>(off, woff, bsum);        // #7
    sort_kernel<<<(EE + 255) / 256, 256, 0, s2>>>(ei, etype, woff, ssrc); // #8
    cudaEventRecord(evJoin, s2);
    cudaStreamWaitEvent(0, evJoin, 0);

    scatter_kernel<<<(NN + 7) / 8, 256>>>(y, off, ssrc, h);            // #9
    bn_stats<<<1024, 256>>>(h, acc);                                   // #10
    bn_final<<<1, 64>>>(acc, gamma1, beta1, scale, shift);             // #11
    gemm_kernel<true><<<MT, 256, SMEM_BYTES>>>(h, wp2, b2, scale, shift, y, out); // #12
    scatter_kernel<<<(NN + 7) / 8, 256>>>(y, off, ssrc, out);          // #13
}

// round 16
// speedup vs baseline: 1.2063x; 1.0123x over previous
#include <cuda_runtime.h>
#include <cuda_bf16.h>
#include <cuda_fp16.h>
#include <cstdint>

#define NN 100000
#define EE 1600000
#define NSEG (NN * 8)
#define AST 136                 // A smem row stride (half): [Xh 64 | Xl 64 | pad 8]
#define SMEM_BYTES (64*AST*2)   // 17408

__device__ __align__(16) __half   g_y[(size_t)NN * 512];
__device__ __align__(16) float    g_h[(size_t)NN * 64];
__device__ __align__(16) unsigned g_cnt[NSEG];
__device__ __align__(16) unsigned g_off[NSEG + 1];
__device__ __align__(16) unsigned g_woff[NSEG];
__device__ __align__(16) unsigned g_bsum[512];
__device__ __align__(16) int      g_ssrc[EE];
__device__ __align__(16) float    g_acc[128];
__device__ __align__(16) float    g_scale[64];
__device__ __align__(16) float    g_shift[64];
// fragment-packed W (fp16): [nc 9][ns 4][kt 4][lane 32] uint4
__device__ __align__(16) __half g_wp1[9 * 4096];
__device__ __align__(16) __half g_wp2[9 * 4096];

// ---------------- prep ----------------
__global__ void hist_kernel(const int* __restrict__ ei, const int* __restrict__ et,
                            unsigned* __restrict__ cnt) {
    int e = blockIdx.x * 256 + threadIdx.x;
    if (e >= EE) return;
    atomicAdd(cnt + ei[EE + e] * 8 + et[e], 1u);
}

__global__ void scan1(const unsigned* __restrict__ cnt, unsigned* __restrict__ off,
                      unsigned* __restrict__ bsum) {
    __shared__ unsigned sh[256];
    int t = threadIdx.x;
    int base = blockIdx.x * 2048 + t * 8;
    unsigned v[8], s = 0;
#pragma unroll
    for (int j = 0; j < 8; j++) { v[j] = (base + j < NSEG) ? cnt[base + j] : 0u; s += v[j]; }
    sh[t] = s; __syncthreads();
    for (int d = 1; d < 256; d <<= 1) {
        unsigned x = (t >= d) ? sh[t - d] : 0u;
        __syncthreads(); sh[t] += x; __syncthreads();
    }
    if (t == 255) bsum[blockIdx.x] = sh[255];
    unsigned run = sh[t] - s;
#pragma unroll
    for (int j = 0; j < 8; j++)
        if (base + j < NSEG) { off[base + j] = run; run += v[j]; }
}

__global__ void scan2(unsigned* bsum, int nb) {
    __shared__ unsigned sh[512];
    int t = threadIdx.x;
    unsigned v = (t < nb) ? bsum[t] : 0u;
    sh[t] = v; __syncthreads();
    for (int d = 1; d < 512; d <<= 1) {
        unsigned x = (t >= d) ? sh[t - d] : 0u;
        __syncthreads(); sh[t] += x; __syncthreads();
    }
    if (t < nb) bsum[t] = sh[t] - v;
}

__global__ void scan3(unsigned* __restrict__ off, unsigned* __restrict__ woff,
                      const unsigned* __restrict__ bsum) {
    int i = blockIdx.x * 256 + threadIdx.x;
    if (i < NSEG) { unsigned o = off[i] + bsum[i >> 11]; off[i] = o; woff[i] = o; }
    if (i == 0) off[NSEG] = EE;
}

__global__ void sort_kernel(const int* __restrict__ ei, const int* __restrict__ et,
                            unsigned* __restrict__ woff, int* __restrict__ ssrc) {
    int e = blockIdx.x * 256 + threadIdx.x;
    if (e >= EE) return;
    int r = et[e];
    int b = ei[EE + e] * 8 + r;
    unsigned pos = atomicAdd(woff + b, 1u);
    ssrc[pos] = ei[e] * 8 + r;
}

// fragment-pack W (+root as rel 8), fp16.
// elem idx: (((nc*4+ns)*4+kt)*32 + lane)*8 + r*2 + p
__global__ void prep_w(const float* __restrict__ w, const float* __restrict__ root,
                       __half* __restrict__ wp) {
    int i = blockIdx.x * 256 + threadIdx.x;
    if (i >= 9 * 4096) return;
    int nc = i >> 12;
    int rem = i & 4095;
    int ns = rem >> 10;
    int rem2 = rem & 1023;
    int kt = rem2 >> 8;
    int rem3 = rem2 & 255;
    int lane = rem3 >> 3;
    int q = rem3 & 7;
    int r = q >> 1, p = q & 1;
    int n_local = ns * 16 + (r >> 1) * 8 + (lane >> 2);
    int j = nc * 64 + n_local;
    int k = kt * 16 + (lane & 3) * 2 + (r & 1) * 8 + p;
    int rel = j >> 6, o = j & 63;
    float v = (rel < 8) ? w[((size_t)rel * 64 + k) * 64 + o] : root[(size_t)k * 64 + o];
    wp[i] = __float2half(v);
}

// ---------------- GEMM: barrier-free, fp16 2-term, depth-2 B prefetch ----------------
__device__ __forceinline__ uint32_t smem_u32(const void* p) {
    uint32_t a;
    asm("{ .reg .u64 t; cvta.to.shared.u64 t, %1; cvt.u32.u64 %0, t; }" : "=r"(a) : "l"(p));
    return a;
}
__device__ __forceinline__ void ldsm4(unsigned& r0, unsigned& r1, unsigned& r2, unsigned& r3,
                                      uint32_t addr) {
    asm volatile("ldmatrix.sync.aligned.m8n8.x4.shared.b16 {%0,%1,%2,%3}, [%4];"
                 : "=r"(r0), "=r"(r1), "=r"(r2), "=r"(r3) : "r"(addr));
}

#define MMAF16(c0,c1,c2,c3,a0,a1,a2,a3,b0,b1)                                       \
    asm volatile("mma.sync.aligned.m16n8k16.row.col.f32.f16.f16.f32 "               \
                 "{%0,%1,%2,%3},{%4,%5,%6,%7},{%8,%9},{%0,%1,%2,%3};"               \
                 : "+f"(c0), "+f"(c1), "+f"(c2), "+f"(c3)                           \
                 : "r"(a0), "r"(a1), "r"(a2), "r"(a3), "r"(b0), "r"(b1))

template <bool APPLY_BN>
__global__ void __launch_bounds__(256, 2)
gemm_kernel(const float* __restrict__ X, const __half* __restrict__ WP,
            const float* __restrict__ bias,
            const float* __restrict__ bnscale, const float* __restrict__ bnshift,
            __half* __restrict__ Y, float* __restrict__ OUT) {
    extern __shared__ char smem[];
    __half* As = (__half*)smem;          // [64][AST]

    const int tid = threadIdx.x;
    const int wid = tid >> 5, lane = tid & 31;
    const int g = lane >> 2, tig = lane & 3;
    const int warpM = wid & 1, ns = wid >> 1;          // m32 x n16 warp tiles
    const int mbase = blockIdx.x * 64;
    const int mat = lane >> 3, rl = lane & 7;

    // A fill: 64 rows x 32 float2 -> fp16 hi/lo
    for (int it = tid; it < 64 * 32; it += 256) {
        int row = it >> 5, dp = it & 31;
        int grow = mbase + row;
        float2 v = make_float2(0.f, 0.f);
        if (grow < NN) v = *(const float2*)(X + (size_t)grow * 64 + dp * 2);
        if (APPLY_BN) {
            v.x = fmaxf(v.x * bnscale[dp * 2]     + bnshift[dp * 2], 0.f);
            v.y = fmaxf(v.y * bnscale[dp * 2 + 1] + bnshift[dp * 2 + 1], 0.f);
        }
        __half2 hi, lo;
        hi.x = __float2half(v.x); hi.y = __float2half(v.y);
        lo.x = __float2half(v.x - __half2float(hi.x));
        lo.y = __float2half(v.y - __half2float(hi.y));
        __half2* arow = (__half2*)(As + row * AST);
        arow[dp] = hi; arow[32 + dp] = lo;
    }
    __syncthreads();    // the ONLY block barrier

    // A frags -> registers once via ldmatrix
    const uint32_t as_u = smem_u32(As);
    unsigned ah[2][4][4], al[2][4][4];
#pragma unroll
    for (int mt = 0; mt < 2; mt++) {
#pragma unroll
        for (int kt = 0; kt < 4; kt++) {
            uint32_t row = warpM * 32 + mt * 16 + (mat & 1) * 8 + rl;
            uint32_t kc  = kt * 16 + (mat >> 1) * 8;
            uint32_t ad = as_u + (row * AST + kc) * 2;
            ldsm4(ah[mt][kt][0], ah[mt][kt][1], ah[mt][kt][2], ah[mt][kt][3], ad);
            ldsm4(al[mt][kt][0], al[mt][kt][1], al[mt][kt][2], al[mt][kt][3], ad + 128);
        }
    }

    float c[2][2][4];
#pragma unroll
    for (int mt = 0; mt < 2; mt++)
#pragma unroll
        for (int nt = 0; nt < 2; nt++)
#pragma unroll
            for (int k = 0; k < 4; k++) c[mt][nt][k] = 0.f;

    // B frag base (uint4 units): step*32 units where step = nc*4+kt; layout stride:
    // nc*512 + ns*128 + kt*32 + lane  ==  (nc*16 + kt)*32 + ns*128 + lane
    const uint4* wb = (const uint4*)WP + ns * 128 + lane;
    // flat step s in [0,36): addr = wb + (s>>2)*512 + (s&3)*32
#define BFRAG(s) __ldg(wb + ((s) >> 2) * 512 + ((s) & 3) * 32)

    uint4 b0 = BFRAG(0);
    uint4 b1 = BFRAG(1);

#pragma unroll 1
    for (int nc = 0; nc < 9; nc++) {
#pragma unroll
        for (int kt = 0; kt < 4; kt++) {
            int s = nc * 4 + kt + 2;
            if (s > 35) s = 35;
            uint4 nb = BFRAG(s);

#pragma unroll
            for (int mt = 0; mt < 2; mt++) {
                MMAF16(c[mt][0][0], c[mt][0][1], c[mt][0][2], c[mt][0][3],
                       ah[mt][kt][0], ah[mt][kt][1], ah[mt][kt][2], ah[mt][kt][3],
                       b0.x, b0.y);
                MMAF16(c[mt][1][0], c[mt][1][1], c[mt][1][2], c[mt][1][3],
                       ah[mt][kt][0], ah[mt][kt][1], ah[mt][kt][2], ah[mt][kt][3],
                       b0.z, b0.w);
                MMAF16(c[mt][0][0], c[mt][0][1], c[mt][0][2], c[mt][0][3],
                       al[mt][kt][0], al[mt][kt][1], al[mt][kt][2], al[mt][kt][3],
                       b0.x, b0.y);
                MMAF16(c[mt][1][0], c[mt][1][1], c[mt][1][2], c[mt][1][3],
                       al[mt][kt][0], al[mt][kt][1], al[mt][kt][2], al[mt][kt][3],
                       b0.z, b0.w);
            }
            b0 = b1; b1 = nb;
        }

        // epilogue for this 64-col chunk
#pragma unroll
        for (int mt = 0; mt < 2; mt++) {
            int row = mbase + warpM * 32 + mt * 16 + g;
#pragma unroll
            for (int nt = 0; nt < 2; nt++) {
                int col = ns * 16 + nt * 8 + 2 * tig;
                float* cc = c[mt][nt];
                if (nc < 8) {
                    size_t base = (size_t)row * 512 + nc * 64 + col;
                    if (row < NN)
                        *(__half2*)(Y + base) = __floats2half2_rn(cc[0], cc[1]);
                    if (row + 8 < NN)
                        *(__half2*)(Y + base + 8 * 512) = __floats2half2_rn(cc[2], cc[3]);
                } else {
                    float2 bb = *(const float2*)(bias + col);
                    if (row < NN)
                        *(float2*)(OUT + (size_t)row * 64 + col) = make_float2(cc[0] + bb.x, cc[1] + bb.y);
                    if (row + 8 < NN)
                        *(float2*)(OUT + (size_t)(row + 8) * 64 + col) = make_float2(cc[2] + bb.x, cc[3] + bb.y);
                }
                cc[0] = cc[1] = cc[2] = cc[3] = 0.f;
            }
        }
    }
#undef BFRAG
}

// ---------------- scatter: warp-per-dst segment reduce, fp16 Y ----------------
__global__ void __launch_bounds__(256)
scatter_kernel(const __half* __restrict__ Y, const unsigned* __restrict__ off,
               const int* __restrict__ ssrc, float* __restrict__ OUT) {
    int node = blockIdx.x * 8 + (threadIdx.x >> 5);
    if (node >= NN) return;
    int lane = threadIdx.x & 31;

    unsigned ov = (lane < 9) ? __ldg(off + (size_t)node * 8 + lane) : 0u;
    unsigned onext = __shfl_down_sync(0xffffffffu, ov, 1);
    float invv = 1.0f / fmaxf((float)(onext - ov), 1.0f);
    unsigned o0 = __shfl_sync(0xffffffffu, ov, 0);
    unsigned o8 = __shfl_sync(0xffffffffu, ov, 8);

    float accx = 0.f, accy = 0.f;
    for (unsigned e = o0; e < o8; e += 4) {
        int sa[4];
#pragma unroll
        for (int j = 0; j < 4; j++)
            sa[j] = (e + j < o8) ? __ldg(ssrc + e + j) : -1;
        float2 v[4];
#pragma unroll
        for (int j = 0; j < 4; j++) {
            v[j] = make_float2(0.f, 0.f);
            if (sa[j] >= 0) {
                __half2 hv = *(const __half2*)(Y + (size_t)sa[j] * 64 + lane * 2);
                v[j] = __half22float2(hv);
            }
        }
#pragma unroll
        for (int j = 0; j < 4; j++) {
            if (sa[j] >= 0) {
                float iv = __shfl_sync(0xffffffffu, invv, sa[j] & 7);
                accx += v[j].x * iv; accy += v[j].y * iv;
            }
        }
    }
    float2* op = (float2*)(OUT + (size_t)node * 64 + lane * 2);
    float2 cur = *op;
    *op = make_float2(cur.x + accx, cur.y + accy);
}

// ---------------- batch norm ----------------
__global__ void bn_stats(const float* __restrict__ H, float* __restrict__ acc) {
    int ch = threadIdx.x & 63, ry = threadIdx.x >> 6;
    float s = 0.f, q = 0.f;
    for (int r = blockIdx.x * 4 + ry; r < NN; r += gridDim.x * 4) {
        float v = H[(size_t)r * 64 + ch];
        s += v; q += v * v;
    }
    __shared__ float sh[2][4][64];
    sh[0][ry][ch] = s; sh[1][ry][ch] = q;
    __syncthreads();
    if (ry == 0) {
        s = sh[0][0][ch] + sh[0][1][ch] + sh[0][2][ch] + sh[0][3][ch];
        q = sh[1][0][ch] + sh[1][1][ch] + sh[1][2][ch] + sh[1][3][ch];
        atomicAdd(acc + ch, s);
        atomicAdd(acc + 64 + ch, q);
    }
}

__global__ void bn_final(const float* __restrict__ acc, const float* __restrict__ gamma,
                         const float* __restrict__ beta,
                         float* __restrict__ scale, float* __restrict__ shift) {
    int ch = threadIdx.x;
    if (ch >= 64) return;
    const float invN = 1.0f / (float)NN;
    float mu = acc[ch] * invN;
    float var = acc[64 + ch] * invN - mu * mu;
    float sc = gamma[ch] * rsqrtf(var + 1e-5f);
    scale[ch] = sc;
    shift[ch] = beta[ch] - mu * sc;
}

// ---------------- launcher ----------------
extern "C" void kernel_launch(void* const* d_in, const int* in_sizes, int n_in,
                              void* d_out, int out_size) {
    const float* x      = (const float*)d_in[0];
    const int*   ei     = (const int*)d_in[1];
    const int*   etype  = (const int*)d_in[2];
    const float* w1     = (const float*)d_in[3];
    const float* root1  = (const float*)d_in[4];
    const float* b1     = (const float*)d_in[5];
    const float* gamma1 = (const float*)d_in[6];
    const float* beta1  = (const float*)d_in[7];
    const float* w2     = (const float*)d_in[8];
    const float* root2  = (const float*)d_in[9];
    const float* b2     = (const float*)d_in[10];
    float* out = (float*)d_out;

    __half *y;
    float *h, *acc, *scale, *shift;
    unsigned *cnt, *off, *woff, *bsum;
    int *ssrc;
    __half *wp1, *wp2;
    cudaGetSymbolAddress((void**)&y, g_y);
    cudaGetSymbolAddress((void**)&h, g_h);
    cudaGetSymbolAddress((void**)&cnt, g_cnt);
    cudaGetSymbolAddress((void**)&off, g_off);
    cudaGetSymbolAddress((void**)&woff, g_woff);
    cudaGetSymbolAddress((void**)&bsum, g_bsum);
    cudaGetSymbolAddress((void**)&ssrc, g_ssrc);
    cudaGetSymbolAddress((void**)&acc, g_acc);
    cudaGetSymbolAddress((void**)&scale, g_scale);
    cudaGetSymbolAddress((void**)&shift, g_shift);
    cudaGetSymbolAddress((void**)&wp1, g_wp1);
    cudaGetSymbolAddress((void**)&wp2, g_wp2);

    cudaFuncSetAttribute(gemm_kernel<false>, cudaFuncAttributeMaxDynamicSharedMemorySize, SMEM_BYTES);
    cudaFuncSetAttribute(gemm_kernel<true>,  cudaFuncAttributeMaxDynamicSharedMemorySize, SMEM_BYTES);

    static cudaStream_t s2 = nullptr;
    static cudaEvent_t evFork = nullptr, evJoin = nullptr;
    if (!s2) {
        cudaStreamCreate(&s2);
        cudaEventCreateWithFlags(&evFork, cudaEventDisableTiming);
        cudaEventCreateWithFlags(&evJoin, cudaEventDisableTiming);
    }

    const int MT = (NN + 63) / 64;             // 1563
    const int NB1 = (NSEG + 2047) / 2048;      // 391
    const int WPN = (9 * 4096 + 255) / 256;    // 144

    cudaMemsetAsync(acc, 0, 128 * sizeof(float), 0);

    prep_w<<<WPN, 256>>>(w1, root1, wp1);                              // #1 (s0)

    // fork: prep_w2 + sort pipeline on s2 (overlap gemm1)
    cudaEventRecord(evFork, 0);
    cudaStreamWaitEvent(s2, evFork, 0);
    cudaMemsetAsync(cnt, 0, NSEG * sizeof(unsigned), s2);
    prep_w<<<WPN, 256, 0, s2>>>(w2, root2, wp2);                       // #2 (s2)
    hist_kernel<<<(EE + 255) / 256, 256, 0, s2>>>(ei, etype, cnt);     // #3 (s2)

    gemm_kernel<false><<<MT, 256, SMEM_BYTES>>>(x, wp1, b1, nullptr, nullptr, y, h); // #4 (profiled)

    scan1<<<NB1, 256, 0, s2>>>(cnt, off, bsum);                        // #5
    scan2<<<1, 512, 0, s2>>>(bsum, NB1);                               // #6
    scan3<<<(NSEG + 255) / 256, 256, 0, s2>>>(off, woff, bsum);        // #7
    sort_kernel<<<(EE + 255) / 256, 256, 0, s2>>>(ei, etype, woff, ssrc); // #8
    cudaEventRecord(evJoin, s2);
    cudaStreamWaitEvent(0, evJoin, 0);

    scatter_kernel<<<(NN + 7) / 8, 256>>>(y, off, ssrc, h);            // #9
    bn_stats<<<1024, 256>>>(h, acc);                                   // #10
    bn_final<<<1, 64>>>(acc, gamma1, beta1, scale, shift);             // #11
    gemm_kernel<true><<<MT, 256, SMEM_BYTES>>>(h, wp2, b2, scale, shift, y, out); // #12
    scatter_kernel<<<(NN + 7) / 8, 256>>>(y, off, ssrc, out);          // #13
}